// round 5
// baseline (speedup 1.0000x reference)
#include <cuda_runtime.h>
#include <math.h>

#define B     64
#define N     196
#define TT    32
#define STEPS 31
#define VOCAB 32000
#define EMB   256
#define HDIM  512
#define VDIM  256
#define ATTD  256
#define G4    2048

// ---------------- scratch (device globals; no allocation) ----------------
__device__ float g_Uv[B * N * ATTD];     // V @ U_att, precomputed once
__device__ float g_h[B * HDIM];
__device__ float g_c[B * HDIM];
__device__ float g_e[B * N];
__device__ float g_ctx[B * VDIM];
__device__ float g_hp[B * EMB];          // h_new @ W_proj
__device__ float g_gpart[4 * B * G4];    // split-K partials for gates GEMM

__device__ __forceinline__ float sigmoidf_(float x) { return 1.f / (1.f + expf(-x)); }
__device__ __forceinline__ float tanh_fast(float x) {
    float y;
    asm("tanh.approx.f32 %0, %1;" : "=f"(y) : "f"(x));
    return y;
}

// ---------------- init: feat_mean -> h0, c0 ----------------
// grid = B, block = 512
__global__ void k_init_hc(const float* __restrict__ V,
                          const float* __restrict__ Wh, const float* __restrict__ bh,
                          const float* __restrict__ Wc, const float* __restrict__ bc) {
    int b = blockIdx.x, tid = threadIdx.x;
    __shared__ float fm[VDIM];
    if (tid < VDIM) {
        const float* vp = V + (size_t)b * N * VDIM + tid;
        float s = 0.f;
        for (int n = 0; n < N; n++) s += vp[(size_t)n * VDIM];
        fm[tid] = s * (1.f / (float)N);
    }
    __syncthreads();
    int j = tid;  // 512 threads, one per HDIM
    float ah = bh[j], ac = bc[j];
    #pragma unroll 4
    for (int v = 0; v < VDIM; v++) {
        float f = fm[v];
        ah += f * Wh[(size_t)v * HDIM + j];
        ac += f * Wc[(size_t)v * HDIM + j];
    }
    g_h[b * HDIM + j] = tanhf(ah);
    g_c[b * HDIM + j] = tanhf(ac);
}

// ---------------- Uv = V @ U_att (once) ----------------
// grid = B*N/16 = 784, block = 256
#define UV_ROWS 16
__global__ void k_uv(const float* __restrict__ V, const float* __restrict__ U) {
    __shared__ float Vs[UV_ROWS * VDIM];
    int r0 = blockIdx.x * UV_ROWS;
    int tid = threadIdx.x;
    for (int i = tid; i < UV_ROWS * VDIM; i += 256)
        Vs[i] = V[(size_t)r0 * VDIM + i];
    __syncthreads();
    float acc[UV_ROWS];
    #pragma unroll
    for (int i = 0; i < UV_ROWS; i++) acc[i] = 0.f;
    int a = tid;
    #pragma unroll 4
    for (int v = 0; v < VDIM; v++) {
        float u = U[(size_t)v * ATTD + a];
        #pragma unroll
        for (int i = 0; i < UV_ROWS; i++) acc[i] += Vs[i * VDIM + v] * u;
    }
    #pragma unroll
    for (int i = 0; i < UV_ROWS; i++)
        g_Uv[(size_t)(r0 + i) * ATTD + a] = acc[i];
}

// ---------------- attention energies ----------------
// grid = dim3(B, 7), block = 256; each block: 28 n's for one b
__global__ void k_att_e(const float* __restrict__ Watt, const float* __restrict__ vatt) {
    int b = blockIdx.x;
    int n0 = blockIdx.y * 28;
    int tid = threadIdx.x;
    __shared__ float hs[HDIM];
    __shared__ float hWs[ATTD];
    __shared__ float vs[ATTD];
    hs[tid]       = g_h[b * HDIM + tid];
    hs[tid + 256] = g_h[b * HDIM + tid + 256];
    vs[tid] = vatt[tid];
    __syncthreads();
    float acc = 0.f;
    #pragma unroll 8
    for (int k = 0; k < HDIM; k++) acc += hs[k] * Watt[(size_t)k * ATTD + tid];
    hWs[tid] = acc;
    __syncthreads();
    int warp = tid >> 5, lane = tid & 31;
    for (int n = n0 + warp; n < n0 + 28; n += 8) {
        const float* uv = g_Uv + (size_t)(b * N + n) * ATTD;
        float p = 0.f;
        #pragma unroll
        for (int j = 0; j < 8; j++) {
            int a = lane + 32 * j;
            p += tanh_fast(hWs[a] + uv[a]) * vs[a];
        }
        #pragma unroll
        for (int off = 16; off > 0; off >>= 1)
            p += __shfl_down_sync(0xffffffffu, p, off);
        if (lane == 0) g_e[b * N + n] = p;
    }
}

// ---------------- softmax + ctx ----------------
// grid = B, block = 256
__global__ void k_att_sm_ctx(const float* __restrict__ V) {
    int b = blockIdx.x, tid = threadIdx.x;
    __shared__ float es[N];
    __shared__ float red[256];
    float v = (tid < N) ? g_e[b * N + tid] : -INFINITY;
    red[tid] = v;
    __syncthreads();
    for (int s = 128; s > 0; s >>= 1) {
        if (tid < s) red[tid] = fmaxf(red[tid], red[tid + s]);
        __syncthreads();
    }
    float mx = red[0];
    __syncthreads();
    float ex = (tid < N) ? expf(v - mx) : 0.f;
    red[tid] = ex;
    __syncthreads();
    for (int s = 128; s > 0; s >>= 1) {
        if (tid < s) red[tid] += red[tid + s];
        __syncthreads();
    }
    float inv = 1.f / red[0];
    __syncthreads();
    if (tid < N) es[tid] = ex * inv;
    __syncthreads();
    const float* vp = V + (size_t)b * N * VDIM + tid;
    float acc = 0.f;
    #pragma unroll 4
    for (int n = 0; n < N; n++) acc += es[n] * vp[(size_t)n * VDIM];
    g_ctx[b * VDIM + tid] = acc;
}

// ---------------- gates GEMM: [64,1024] @ [1024,2048], split-K ----------------
// grid = dim3(32 jtiles, 4 kchunks), block = 256, dyn smem = 135168
__global__ void k_gates(const float* __restrict__ embed, const int* __restrict__ y,
                        const float* __restrict__ Wih, const float* __restrict__ Whh, int t) {
    extern __shared__ float sm[];
    float* Xs = sm;               // [256 kk][68 pad] holds X^T tile (bb fastest)
    float* Ws = sm + 256 * 68;    // [256 kk][64 jj]
    int j0 = blockIdx.x * 64;
    int kc = blockIdx.y;
    int tid = threadIdx.x;

    for (int idx = tid; idx < B * 256; idx += 256) {
        int kk = idx & 255, bb = idx >> 8;
        float x;
        if (kc == 0)      x = embed[(size_t)y[bb * TT + t] * EMB + kk];
        else if (kc == 1) x = g_ctx[bb * VDIM + kk];
        else if (kc == 2) x = g_h[bb * HDIM + kk];
        else              x = g_h[bb * HDIM + 256 + kk];
        Xs[kk * 68 + bb] = x;
    }
    const float* W = (kc < 2) ? (Wih + (size_t)(kc * 256) * G4)
                              : (Whh + (size_t)((kc - 2) * 256) * G4);
    for (int idx = tid; idx < 256 * 64; idx += 256) {
        int kk = idx >> 6, jj = idx & 63;
        Ws[idx] = W[(size_t)kk * G4 + j0 + jj];
    }
    __syncthreads();

    int tx = tid & 15, ty = tid >> 4;
    float acc[4][4];
    #pragma unroll
    for (int i = 0; i < 4; i++)
        #pragma unroll
        for (int j = 0; j < 4; j++) acc[i][j] = 0.f;

    #pragma unroll 4
    for (int kk = 0; kk < 256; kk++) {
        float4 xf = *(const float4*)&Xs[kk * 68 + ty * 4];
        float4 wf = *(const float4*)&Ws[kk * 64 + tx * 4];
        acc[0][0] += xf.x * wf.x; acc[0][1] += xf.x * wf.y; acc[0][2] += xf.x * wf.z; acc[0][3] += xf.x * wf.w;
        acc[1][0] += xf.y * wf.x; acc[1][1] += xf.y * wf.y; acc[1][2] += xf.y * wf.z; acc[1][3] += xf.y * wf.w;
        acc[2][0] += xf.z * wf.x; acc[2][1] += xf.z * wf.y; acc[2][2] += xf.z * wf.z; acc[2][3] += xf.z * wf.w;
        acc[3][0] += xf.w * wf.x; acc[3][1] += xf.w * wf.y; acc[3][2] += xf.w * wf.z; acc[3][3] += xf.w * wf.w;
    }
    float* gp = g_gpart + (size_t)kc * B * G4;
    #pragma unroll
    for (int i = 0; i < 4; i++) {
        int bb = ty * 4 + i;
        *(float4*)&gp[(size_t)bb * G4 + j0 + tx * 4] =
            make_float4(acc[i][0], acc[i][1], acc[i][2], acc[i][3]);
    }
}

// ---------------- LSTM update + hp = h_new @ W_proj ----------------
// grid = B, block = 512
__global__ void k_lstm_hp(const float* __restrict__ bih, const float* __restrict__ bhh,
                          const float* __restrict__ Wproj) {
    int b = blockIdx.x, tid = threadIdx.x;
    __shared__ float hn[HDIM];
    int j = tid;
    float gi = bih[j]        + bhh[j];
    float gf = bih[512 + j]  + bhh[512 + j];
    float gg = bih[1024 + j] + bhh[1024 + j];
    float go = bih[1536 + j] + bhh[1536 + j];
    #pragma unroll
    for (int kc = 0; kc < 4; kc++) {
        const float* gp = g_gpart + (size_t)kc * B * G4 + (size_t)b * G4;
        gi += gp[j]; gf += gp[512 + j]; gg += gp[1024 + j]; go += gp[1536 + j];
    }
    float c = sigmoidf_(gf) * g_c[b * HDIM + j] + sigmoidf_(gi) * tanhf(gg);
    float h = sigmoidf_(go) * tanhf(c);
    g_c[b * HDIM + j] = c;
    g_h[b * HDIM + j] = h;
    hn[j] = h;
    __syncthreads();
    if (tid < EMB) {
        float acc = 0.f;
        #pragma unroll 8
        for (int k = 0; k < HDIM; k++) acc += hn[k] * Wproj[(size_t)k * EMB + tid];
        g_hp[b * EMB + tid] = acc;
    }
}

// ---------------- logits = hp @ embed^T ----------------
// grid = VOCAB/64 = 500, block = 256, dyn smem = 139264
__global__ void k_logits(const float* __restrict__ embed, float* __restrict__ out, int t) {
    extern __shared__ float sm[];
    float* Hs = sm;               // [256 kk][68 pad] : hp^T (bb fastest)
    float* Es = sm + 256 * 68;    // [256 kk][68 pad] : embed^T tile (vv fastest)
    int v0 = blockIdx.x * 64;
    int tid = threadIdx.x;

    for (int idx = tid; idx < B * EMB; idx += 256) {
        int kk = idx & 255, bb = idx >> 8;
        Hs[kk * 68 + bb] = g_hp[bb * EMB + kk];
    }
    for (int idx = tid; idx < 64 * EMB; idx += 256) {
        int kk = idx & 255, vv = idx >> 8;
        Es[kk * 68 + vv] = embed[(size_t)(v0 + vv) * EMB + kk];
    }
    __syncthreads();

    int tx = tid & 15, ty = tid >> 4;
    float acc[4][4];
    #pragma unroll
    for (int i = 0; i < 4; i++)
        #pragma unroll
        for (int j = 0; j < 4; j++) acc[i][j] = 0.f;

    #pragma unroll 4
    for (int kk = 0; kk < 256; kk++) {
        float4 hf = *(const float4*)&Hs[kk * 68 + ty * 4];
        float4 ef = *(const float4*)&Es[kk * 68 + tx * 4];
        acc[0][0] += hf.x * ef.x; acc[0][1] += hf.x * ef.y; acc[0][2] += hf.x * ef.z; acc[0][3] += hf.x * ef.w;
        acc[1][0] += hf.y * ef.x; acc[1][1] += hf.y * ef.y; acc[1][2] += hf.y * ef.z; acc[1][3] += hf.y * ef.w;
        acc[2][0] += hf.z * ef.x; acc[2][1] += hf.z * ef.y; acc[2][2] += hf.z * ef.z; acc[2][3] += hf.z * ef.w;
        acc[3][0] += hf.w * ef.x; acc[3][1] += hf.w * ef.y; acc[3][2] += hf.w * ef.z; acc[3][3] += hf.w * ef.w;
    }
    #pragma unroll
    for (int i = 0; i < 4; i++) {
        int bb = ty * 4 + i;
        float* op = out + ((size_t)bb * STEPS + t) * VOCAB + v0 + tx * 4;
        *(float4*)op = make_float4(acc[i][0], acc[i][1], acc[i][2], acc[i][3]);
    }
}

// ---------------- launch ----------------
extern "C" void kernel_launch(void* const* d_in, const int* in_sizes, int n_in,
                              void* d_out, int out_size) {
    const float* V      = (const float*)d_in[0];
    const int*   y      = (const int*)  d_in[1];
    const float* embed  = (const float*)d_in[2];
    const float* W_att  = (const float*)d_in[3];
    const float* U_att  = (const float*)d_in[4];
    const float* v_att  = (const float*)d_in[5];
    const float* W_ih   = (const float*)d_in[6];
    const float* W_hh   = (const float*)d_in[7];
    const float* b_ih   = (const float*)d_in[8];
    const float* b_hh   = (const float*)d_in[9];
    const float* W_inith = (const float*)d_in[10];
    const float* b_inith = (const float*)d_in[11];
    const float* W_initc = (const float*)d_in[12];
    const float* b_initc = (const float*)d_in[13];
    const float* W_proj  = (const float*)d_in[14];
    float* out = (float*)d_out;

    const int SMEM_GATES  = (256 * 68 + 256 * 64) * sizeof(float);  // 135168
    const int SMEM_LOGITS = (2 * 256 * 68) * sizeof(float);         // 139264
    cudaFuncSetAttribute(k_gates,  cudaFuncAttributeMaxDynamicSharedMemorySize, SMEM_GATES);
    cudaFuncSetAttribute(k_logits, cudaFuncAttributeMaxDynamicSharedMemorySize, SMEM_LOGITS);

    k_init_hc<<<B, 512>>>(V, W_inith, b_inith, W_initc, b_initc);
    k_uv<<<(B * N) / UV_ROWS, 256>>>(V, U_att);

    for (int t = 0; t < STEPS; t++) {
        k_att_e<<<dim3(B, 7), 256>>>(W_att, v_att);
        k_att_sm_ctx<<<B, 256>>>(V);
        k_gates<<<dim3(32, 4), 256, SMEM_GATES>>>(embed, y, W_ih, W_hh, t);
        k_lstm_hp<<<B, 512>>>(b_ih, b_hh, W_proj);
        k_logits<<<VOCAB / 64, 256, SMEM_LOGITS>>>(embed, out, t);
    }
}

// round 6
// speedup vs baseline: 1.3821x; 1.3821x over previous
#include <cuda_runtime.h>
#include <math.h>

#define B     64
#define N     196
#define TT    32
#define STEPS 31
#define VOCAB 32000
#define EMB   256
#define HDIM  512
#define VDIM  256
#define ATTD  256
#define G4    2048

// ---------------- scratch (device globals; no allocation) ----------------
__device__ float g_Uv[B * N * ATTD];     // V @ U_att, precomputed once
__device__ float g_h[B * HDIM];
__device__ float g_c[B * HDIM];
__device__ float g_e[B * N];
__device__ float g_ctxp[4 * B * VDIM];   // 4-way n-split ctx partials
__device__ float g_hp[B * EMB];          // h @ W_proj (reduced)
__device__ float g_hW[B * ATTD];         // h @ W_att  (reduced)
__device__ float g_pp[4 * B * 512];      // split-K partials for [hp|hW] GEMM
__device__ float g_gpart[4 * B * G4];    // split-K partials for gates GEMM

__device__ __forceinline__ float sigmoidf_(float x) { return 1.f / (1.f + expf(-x)); }
__device__ __forceinline__ float tanh_fast(float x) {
    float y;
    asm("tanh.approx.f32 %0, %1;" : "=f"(y) : "f"(x));
    return y;
}

// ---------------- packed f32x2 FMA helpers ----------------
typedef unsigned long long ull;
struct Acc44 { ull a[4][2]; };

__device__ __forceinline__ ull fma2(ull a, ull b, ull c) {
    ull d;
    asm("fma.rn.f32x2 %0, %1, %2, %3;" : "=l"(d) : "l"(a), "l"(b), "l"(c));
    return d;
}
__device__ __forceinline__ ull pack2(float x) {
    ull d; unsigned int xi = __float_as_uint(x);
    asm("mov.b64 %0, {%1, %1};" : "=l"(d) : "r"(xi));
    return d;
}
__device__ __forceinline__ void acc_zero(Acc44& A) {
    #pragma unroll
    for (int i = 0; i < 4; i++) { A.a[i][0] = 0ull; A.a[i][1] = 0ull; }
}
__device__ __forceinline__ void mma44(Acc44& A, float4 xf, ulonglong2 wf) {
    ull h;
    h = pack2(xf.x); A.a[0][0] = fma2(h, wf.x, A.a[0][0]); A.a[0][1] = fma2(h, wf.y, A.a[0][1]);
    h = pack2(xf.y); A.a[1][0] = fma2(h, wf.x, A.a[1][0]); A.a[1][1] = fma2(h, wf.y, A.a[1][1]);
    h = pack2(xf.z); A.a[2][0] = fma2(h, wf.x, A.a[2][0]); A.a[2][1] = fma2(h, wf.y, A.a[2][1]);
    h = pack2(xf.w); A.a[3][0] = fma2(h, wf.x, A.a[3][0]); A.a[3][1] = fma2(h, wf.y, A.a[3][1]);
}
__device__ __forceinline__ float4 unpack44(const Acc44& A, int i) {
    unsigned int l0, h0, l1, h1;
    asm("mov.b64 {%0,%1}, %2;" : "=r"(l0), "=r"(h0) : "l"(A.a[i][0]));
    asm("mov.b64 {%0,%1}, %2;" : "=r"(l1), "=r"(h1) : "l"(A.a[i][1]));
    return make_float4(__uint_as_float(l0), __uint_as_float(h0),
                       __uint_as_float(l1), __uint_as_float(h1));
}

// ---------------- init: feat_mean -> h0, c0 ----------------
// grid = B, block = 512
__global__ void k_init_hc(const float* __restrict__ V,
                          const float* __restrict__ Wh, const float* __restrict__ bh,
                          const float* __restrict__ Wc, const float* __restrict__ bc) {
    int b = blockIdx.x, tid = threadIdx.x;
    __shared__ float fm[VDIM];
    if (tid < VDIM) {
        const float* vp = V + (size_t)b * N * VDIM + tid;
        float s = 0.f;
        for (int n = 0; n < N; n++) s += vp[(size_t)n * VDIM];
        fm[tid] = s * (1.f / (float)N);
    }
    __syncthreads();
    int j = tid;
    float ah = bh[j], ac = bc[j];
    #pragma unroll 4
    for (int v = 0; v < VDIM; v++) {
        float f = fm[v];
        ah += f * Wh[(size_t)v * HDIM + j];
        ac += f * Wc[(size_t)v * HDIM + j];
    }
    g_h[b * HDIM + j] = tanhf(ah);
    g_c[b * HDIM + j] = tanhf(ac);
}

// ---------------- Uv = V @ U_att (once) ----------------
// grid = B*N/16 = 784, block = 256
#define UV_ROWS 16
__global__ void k_uv(const float* __restrict__ V, const float* __restrict__ U) {
    __shared__ float Vs[UV_ROWS * VDIM];
    int r0 = blockIdx.x * UV_ROWS;
    int tid = threadIdx.x;
    for (int i = tid; i < UV_ROWS * VDIM; i += 256)
        Vs[i] = V[(size_t)r0 * VDIM + i];
    __syncthreads();
    float acc[UV_ROWS];
    #pragma unroll
    for (int i = 0; i < UV_ROWS; i++) acc[i] = 0.f;
    int a = tid;
    #pragma unroll 4
    for (int v = 0; v < VDIM; v++) {
        float u = U[(size_t)v * ATTD + a];
        #pragma unroll
        for (int i = 0; i < UV_ROWS; i++) acc[i] += Vs[i * VDIM + v] * u;
    }
    #pragma unroll
    for (int i = 0; i < UV_ROWS; i++)
        g_Uv[(size_t)(r0 + i) * ATTD + a] = acc[i];
}

// ---------------- proj GEMM: [hp|hW] = h[64,512] @ [Wproj|Watt][512,512], split-K ----------------
// grid = dim3(8 jtiles, 4 kchunks), block = 256, dyn smem = 67584
__global__ void k_proj(const float* __restrict__ Wproj, const float* __restrict__ Watt) {
    extern __shared__ float sm[];
    float* Xs = sm;               // [128 kk][68 pad] h^T chunk (bb fastest)
    float* Ws = sm + 128 * 68;    // [128 kk][64 jj]
    int j0 = blockIdx.x * 64;
    int kc = blockIdx.y;
    int tid = threadIdx.x;

    for (int idx = tid; idx < B * 128; idx += 256) {
        int kk = idx & 127, bb = idx >> 7;
        Xs[kk * 68 + bb] = g_h[bb * HDIM + kc * 128 + kk];
    }
    const float* W = (j0 < 256) ? (Wproj + j0) : (Watt + (j0 - 256));
    for (int idx = tid; idx < 128 * 64; idx += 256) {
        int kk = idx >> 6, jj = idx & 63;
        Ws[idx] = W[(size_t)(kc * 128 + kk) * 256 + jj];
    }
    __syncthreads();

    int tx = tid & 15, ty = tid >> 4;
    Acc44 A; acc_zero(A);
    #pragma unroll 4
    for (int kk = 0; kk < 128; kk++) {
        float4 xf = *(const float4*)&Xs[kk * 68 + ty * 4];
        ulonglong2 wf = *(const ulonglong2*)&Ws[kk * 64 + tx * 4];
        mma44(A, xf, wf);
    }
    float* pp = g_pp + (size_t)kc * B * 512;
    #pragma unroll
    for (int i = 0; i < 4; i++) {
        int bb = ty * 4 + i;
        *(float4*)&pp[(size_t)bb * 512 + j0 + tx * 4] = unpack44(A, i);
    }
}

// ---------------- reduce split-K partials -> g_hp, g_hW ----------------
// grid = B, block = 512
__global__ void k_hphw() {
    int b = blockIdx.x, j = threadIdx.x;
    size_t o = (size_t)b * 512 + j;
    float s = g_pp[o] + g_pp[B * 512 + o] + g_pp[2 * B * 512 + o] + g_pp[3 * B * 512 + o];
    if (j < 256) g_hp[b * EMB + j] = s;
    else         g_hW[b * ATTD + (j - 256)] = s;
}

// ---------------- attention energies (hW precomputed) ----------------
// grid = dim3(B, 7), block = 256
__global__ void k_att_e(const float* __restrict__ vatt) {
    int b = blockIdx.x;
    int n0 = blockIdx.y * 28;
    int tid = threadIdx.x;
    __shared__ float hWs[ATTD];
    __shared__ float vs[ATTD];
    hWs[tid] = g_hW[b * ATTD + tid];
    vs[tid] = vatt[tid];
    __syncthreads();
    int warp = tid >> 5, lane = tid & 31;
    for (int n = n0 + warp; n < n0 + 28; n += 8) {
        const float* uv = g_Uv + (size_t)(b * N + n) * ATTD;
        float p = 0.f;
        #pragma unroll
        for (int j = 0; j < 8; j++) {
            int a = lane + 32 * j;
            p += tanh_fast(hWs[a] + uv[a]) * vs[a];
        }
        #pragma unroll
        for (int off = 16; off > 0; off >>= 1)
            p += __shfl_down_sync(0xffffffffu, p, off);
        if (lane == 0) g_e[b * N + n] = p;
    }
}

// ---------------- softmax + ctx partial (4-way split over n) ----------------
// grid = dim3(B, 4), block = 256
__global__ void k_sm_ctx4(const float* __restrict__ V) {
    int b = blockIdx.x, ch = blockIdx.y, tid = threadIdx.x;
    __shared__ float es[N];
    __shared__ float red[256];
    float v = (tid < N) ? g_e[b * N + tid] : -INFINITY;
    red[tid] = v;
    __syncthreads();
    for (int s = 128; s > 0; s >>= 1) {
        if (tid < s) red[tid] = fmaxf(red[tid], red[tid + s]);
        __syncthreads();
    }
    float mx = red[0];
    __syncthreads();
    float ex = (tid < N) ? expf(v - mx) : 0.f;
    red[tid] = ex;
    __syncthreads();
    for (int s = 128; s > 0; s >>= 1) {
        if (tid < s) red[tid] += red[tid + s];
        __syncthreads();
    }
    float inv = 1.f / red[0];
    __syncthreads();
    if (tid < N) es[tid] = ex * inv;
    __syncthreads();
    const float* vp = V + (size_t)b * N * VDIM + (size_t)ch * 49 * VDIM + tid;
    float acc = 0.f;
    #pragma unroll 7
    for (int n = 0; n < 49; n++) acc += es[ch * 49 + n] * vp[(size_t)n * VDIM];
    g_ctxp[ch * B * VDIM + b * VDIM + tid] = acc;
}

// ---------------- gates GEMM: [64,1024] @ [1024,2048], split-K ----------------
// grid = dim3(32, 4), block = 256, dyn smem = 135168
__global__ void k_gates(const float* __restrict__ embed, const int* __restrict__ y,
                        const float* __restrict__ Wih, const float* __restrict__ Whh, int t) {
    extern __shared__ float sm[];
    float* Xs = sm;               // [256 kk][68 pad] X^T tile (bb fastest)
    float* Ws = sm + 256 * 68;    // [256 kk][64 jj]
    int j0 = blockIdx.x * 64;
    int kc = blockIdx.y;
    int tid = threadIdx.x;

    for (int idx = tid; idx < B * 256; idx += 256) {
        int kk = idx & 255, bb = idx >> 8;
        float x;
        if (kc == 0)      x = embed[(size_t)y[bb * TT + t] * EMB + kk];
        else if (kc == 1) x = g_ctxp[bb * VDIM + kk] + g_ctxp[B * VDIM + bb * VDIM + kk]
                            + g_ctxp[2 * B * VDIM + bb * VDIM + kk]
                            + g_ctxp[3 * B * VDIM + bb * VDIM + kk];
        else if (kc == 2) x = g_h[bb * HDIM + kk];
        else              x = g_h[bb * HDIM + 256 + kk];
        Xs[kk * 68 + bb] = x;
    }
    const float* W = (kc < 2) ? (Wih + (size_t)(kc * 256) * G4)
                              : (Whh + (size_t)((kc - 2) * 256) * G4);
    for (int idx = tid; idx < 256 * 64; idx += 256) {
        int kk = idx >> 6, jj = idx & 63;
        Ws[idx] = W[(size_t)kk * G4 + j0 + jj];
    }
    __syncthreads();

    int tx = tid & 15, ty = tid >> 4;
    Acc44 A; acc_zero(A);
    #pragma unroll 4
    for (int kk = 0; kk < 256; kk++) {
        float4 xf = *(const float4*)&Xs[kk * 68 + ty * 4];
        ulonglong2 wf = *(const ulonglong2*)&Ws[kk * 64 + tx * 4];
        mma44(A, xf, wf);
    }
    float* gp = g_gpart + (size_t)kc * B * G4;
    #pragma unroll
    for (int i = 0; i < 4; i++) {
        int bb = ty * 4 + i;
        *(float4*)&gp[(size_t)bb * G4 + j0 + tx * 4] = unpack44(A, i);
    }
}

// ---------------- LSTM update ----------------
// grid = B, block = 512
__global__ void k_lstm(const float* __restrict__ bih, const float* __restrict__ bhh) {
    int b = blockIdx.x, j = threadIdx.x;
    float gi = bih[j]        + bhh[j];
    float gf = bih[512 + j]  + bhh[512 + j];
    float gg = bih[1024 + j] + bhh[1024 + j];
    float go = bih[1536 + j] + bhh[1536 + j];
    #pragma unroll
    for (int kc = 0; kc < 4; kc++) {
        const float* gp = g_gpart + (size_t)kc * B * G4 + (size_t)b * G4;
        gi += gp[j]; gf += gp[512 + j]; gg += gp[1024 + j]; go += gp[1536 + j];
    }
    float c = sigmoidf_(gf) * g_c[b * HDIM + j] + sigmoidf_(gi) * tanhf(gg);
    float h = sigmoidf_(go) * tanhf(c);
    g_c[b * HDIM + j] = c;
    g_h[b * HDIM + j] = h;
}

// ---------------- logits = hp @ embed^T (K chunked, f32x2) ----------------
// grid = VOCAB/64 = 500, block = 256, dyn smem = 69632
__global__ void k_logits(const float* __restrict__ embed, float* __restrict__ out, int t) {
    extern __shared__ float sm[];
    float* Hs = sm;               // [128 kk][68 pad] : hp^T chunk (bb fastest)
    float* Es = sm + 128 * 68;    // [128 kk][68 pad] : embed^T chunk (vv fastest)
    int v0 = blockIdx.x * 64;
    int tid = threadIdx.x;
    int tx = tid & 15, ty = tid >> 4;

    Acc44 A; acc_zero(A);
    #pragma unroll
    for (int kc2 = 0; kc2 < 2; kc2++) {
        int kb = kc2 * 128;
        for (int idx = tid; idx < B * 128; idx += 256) {
            int kk = idx & 127, bb = idx >> 7;
            Hs[kk * 68 + bb] = g_hp[bb * EMB + kb + kk];
        }
        for (int idx = tid; idx < 64 * 128; idx += 256) {
            int kk = idx & 127, vv = idx >> 7;
            Es[kk * 68 + vv] = embed[(size_t)(v0 + vv) * EMB + kb + kk];
        }
        __syncthreads();
        #pragma unroll 4
        for (int kk = 0; kk < 128; kk++) {
            float4 hf = *(const float4*)&Hs[kk * 68 + ty * 4];
            ulonglong2 ef = *(const ulonglong2*)&Es[kk * 68 + tx * 4];
            mma44(A, hf, ef);
        }
        __syncthreads();
    }
    #pragma unroll
    for (int i = 0; i < 4; i++) {
        int bb = ty * 4 + i;
        float* op = out + ((size_t)bb * STEPS + t) * VOCAB + v0 + tx * 4;
        *(float4*)op = unpack44(A, i);
    }
}

// ---------------- launch ----------------
extern "C" void kernel_launch(void* const* d_in, const int* in_sizes, int n_in,
                              void* d_out, int out_size) {
    const float* V      = (const float*)d_in[0];
    const int*   y      = (const int*)  d_in[1];
    const float* embed  = (const float*)d_in[2];
    const float* W_att  = (const float*)d_in[3];
    const float* U_att  = (const float*)d_in[4];
    const float* v_att  = (const float*)d_in[5];
    const float* W_ih   = (const float*)d_in[6];
    const float* W_hh   = (const float*)d_in[7];
    const float* b_ih   = (const float*)d_in[8];
    const float* b_hh   = (const float*)d_in[9];
    const float* W_inith = (const float*)d_in[10];
    const float* b_inith = (const float*)d_in[11];
    const float* W_initc = (const float*)d_in[12];
    const float* b_initc = (const float*)d_in[13];
    const float* W_proj  = (const float*)d_in[14];
    float* out = (float*)d_out;

    const int SMEM_GATES  = (256 * 68 + 256 * 64) * sizeof(float);  // 135168
    const int SMEM_PROJ   = (128 * 68 + 128 * 64) * sizeof(float);  // 67584
    const int SMEM_LOGITS = (2 * 128 * 68) * sizeof(float);         // 69632
    cudaFuncSetAttribute(k_gates,  cudaFuncAttributeMaxDynamicSharedMemorySize, SMEM_GATES);
    cudaFuncSetAttribute(k_proj,   cudaFuncAttributeMaxDynamicSharedMemorySize, SMEM_PROJ);
    cudaFuncSetAttribute(k_logits, cudaFuncAttributeMaxDynamicSharedMemorySize, SMEM_LOGITS);

    k_init_hc<<<B, 512>>>(V, W_inith, b_inith, W_initc, b_initc);
    k_uv<<<(B * N) / UV_ROWS, 256>>>(V, U_att);
    // hW(h0) for step 0 (hp(h0) computed too but unused/overwritten)
    k_proj<<<dim3(8, 4), 256, SMEM_PROJ>>>(W_proj, W_att);
    k_hphw<<<B, 512>>>();

    for (int t = 0; t < STEPS; t++) {
        k_att_e<<<dim3(B, 7), 256>>>(v_att);
        k_sm_ctx4<<<dim3(B, 4), 256>>>(V);
        k_gates<<<dim3(32, 4), 256, SMEM_GATES>>>(embed, y, W_ih, W_hh, t);
        k_lstm<<<B, 512>>>(b_ih, b_hh);
        k_proj<<<dim3(8, 4), 256, SMEM_PROJ>>>(W_proj, W_att);
        k_hphw<<<B, 512>>>();
        k_logits<<<VOCAB / 64, 256, SMEM_LOGITS>>>(embed, out, t);
    }
}